// round 2
// baseline (speedup 1.0000x reference)
#include <cuda_runtime.h>

// Problem constants
#define B_  8
#define S_  4096
#define D_  1024
#define KK  32      // E*P = 8*4

// Output layout: flat concat of (expert_weights, expert_indices, phi_weights,
// soft_slots, expert_inputs), all as float32.
#define OFF0 0              // expert_weights [B,S,E]      262144
#define OFF1 262144         // expert_indices [B,S,E]      262144
#define OFF2 524288         // phi_weights    [B,S,E,P]    1048576
#define OFF3 1572864        // soft_slots     [B,E,P,D]    262144
#define OFF4 1835008        // expert_inputs  [B,E,P*D]    262144

// Scratch (device globals: no allocation allowed)
__device__ float g_L[B_ * KK * S_];        // logits, [b][k][s]   (4 MB)
__device__ float g_part[B_ * 8 * KK * D_]; // split-K partials    (8 MB)

__device__ __forceinline__ unsigned long long fma2(unsigned long long a,
                                                   unsigned long long b,
                                                   unsigned long long c) {
    unsigned long long d;
    asm("fma.rn.f32x2 %0, %1, %2, %3;" : "=l"(d) : "l"(a), "l"(b), "l"(c));
    return d;
}
__device__ __forceinline__ unsigned long long dup2(float p) {
    unsigned long long d;
    asm("mov.b64 %0, {%1, %1};" : "=l"(d) : "f"(p));
    return d;
}
__device__ __forceinline__ float2 unpack2(unsigned long long v) {
    float2 r;
    asm("mov.b64 {%0, %1}, %2;" : "=f"(r.x), "=f"(r.y) : "l"(v));
    return r;
}

// ---------------------------------------------------------------------------
// Phase A: logits[b,k,s] = sum_d x[b,s,d] * phiK[d,k] + bias[k]
// Tile: 128 tokens x 32 k per block, 128 threads, thread = 8 tok x 4 k.
// f32x2 packs token pairs; phi operand dup-packed once per (d, k).
// ---------------------------------------------------------------------------
__global__ void __launch_bounds__(128) phaseA(const float* __restrict__ x,
                                              const float* __restrict__ phiK,
                                              const float* __restrict__ bias) {
    __shared__ __align__(16) float xs[32][130]; // [d][tok], pad keeps 8B align + banks spread
    __shared__ __align__(16) float ps[32][32];  // [d][k]

    const int tid  = threadIdx.x;
    const int tok0 = blockIdx.x * 128;          // never crosses a batch (S % 128 == 0)
    const int b    = tok0 / S_;
    const int s0   = tok0 - b * S_;
    const int tg   = tid & 15;                  // token group: 8 contiguous tokens
    const int tk   = tid >> 4;                  // k group: 4 contiguous k

    unsigned long long acc[4][4];               // [kk][token-pair]
    #pragma unroll
    for (int i = 0; i < 4; i++)
        #pragma unroll
        for (int j = 0; j < 4; j++) acc[i][j] = 0ull;

    for (int dt = 0; dt < 32; dt++) {
        const int dbase = dt * 32;
        __syncthreads();
        // stage x tile transposed: xs[d][tok]
        #pragma unroll
        for (int i = 0; i < 32; i++) {
            int idx = tid + i * 128;
            int d = idx & 31;
            int t = idx >> 5;
            xs[d][t] = x[(size_t)(tok0 + t) * D_ + dbase + d];
        }
        // stage phi tile: ps[d][k]
        #pragma unroll
        for (int i = 0; i < 8; i++) {
            int idx = tid + i * 128;
            int d = idx >> 5;
            int k = idx & 31;
            ps[d][k] = phiK[(size_t)(dbase + d) * KK + k];
        }
        __syncthreads();

        #pragma unroll 8
        for (int d = 0; d < 32; d++) {
            float4 ph = *(const float4*)&ps[d][tk * 4];
            unsigned long long p0 = dup2(ph.x), p1 = dup2(ph.y),
                               p2 = dup2(ph.z), p3 = dup2(ph.w);
            #pragma unroll
            for (int tp = 0; tp < 4; tp++) {
                unsigned long long xv =
                    *(const unsigned long long*)&xs[d][tg * 8 + tp * 2];
                acc[0][tp] = fma2(xv, p0, acc[0][tp]);
                acc[1][tp] = fma2(xv, p1, acc[1][tp]);
                acc[2][tp] = fma2(xv, p2, acc[2][tp]);
                acc[3][tp] = fma2(xv, p3, acc[3][tp]);
            }
        }
    }

    // write logits to [b][k][s] scratch
    #pragma unroll
    for (int kk = 0; kk < 4; kk++) {
        int k = tk * 4 + kk;
        float bv = bias[k];
        float* dst = &g_L[((size_t)b * KK + k) * S_ + s0 + tg * 8];
        #pragma unroll
        for (int tp = 0; tp < 4; tp++) {
            float2 v = unpack2(acc[kk][tp]);
            dst[tp * 2 + 0] = v.x + bv;
            dst[tp * 2 + 1] = v.y + bv;
        }
    }
}

// ---------------------------------------------------------------------------
// Phase B: softmax over S per (b,k); writes normalized weights into the
// phi_weights output region in [b][s][k] layout.
// ---------------------------------------------------------------------------
__global__ void __launch_bounds__(256) phaseB(float* __restrict__ out) {
    const int bk  = blockIdx.x;       // b*32 + k
    const int b   = bk >> 5;
    const int k   = bk & 31;
    const int tid = threadIdx.x;
    const float* L = &g_L[(size_t)bk * S_];

    __shared__ float red[8];

    float v[16];
    float m = -1e30f;
    #pragma unroll
    for (int i = 0; i < 16; i++) {
        v[i] = L[tid + i * 256];
        m = fmaxf(m, v[i]);
    }
    #pragma unroll
    for (int o = 16; o > 0; o >>= 1) m = fmaxf(m, __shfl_xor_sync(0xffffffffu, m, o));
    if ((tid & 31) == 0) red[tid >> 5] = m;
    __syncthreads();
    if (tid < 32) {
        float t = (tid < 8) ? red[tid] : -1e30f;
        #pragma unroll
        for (int o = 4; o > 0; o >>= 1) t = fmaxf(t, __shfl_xor_sync(0xffffffffu, t, o));
        if (tid == 0) red[0] = t;
    }
    __syncthreads();
    m = red[0];
    __syncthreads();

    float s = 0.f;
    #pragma unroll
    for (int i = 0; i < 16; i++) {
        v[i] = __expf(v[i] - m);
        s += v[i];
    }
    #pragma unroll
    for (int o = 16; o > 0; o >>= 1) s += __shfl_xor_sync(0xffffffffu, s, o);
    if ((tid & 31) == 0) red[tid >> 5] = s;
    __syncthreads();
    if (tid < 32) {
        float t = (tid < 8) ? red[tid] : 0.f;
        #pragma unroll
        for (int o = 4; o > 0; o >>= 1) t += __shfl_xor_sync(0xffffffffu, t, o);
        if (tid == 0) red[0] = t;
    }
    __syncthreads();
    const float inv = 1.0f / red[0];

    float* dst = out + OFF2 + (size_t)b * S_ * KK + k;
    #pragma unroll
    for (int i = 0; i < 16; i++) {
        int sidx = tid + i * 256;
        dst[(size_t)sidx * KK] = v[i] * inv;
    }
}

// ---------------------------------------------------------------------------
// Phase C: partial[b,sp,k,d] = sum_{s in split sp} x[b,s,d] * w[b,s,k]
// Grid 512 = B x 8 d-tiles x 8 S-splits. 128 threads, thread = 4 k x 8 d.
// ---------------------------------------------------------------------------
__global__ void __launch_bounds__(128) phaseC(const float* __restrict__ x,
                                              const float* __restrict__ out) {
    const int bid = blockIdx.x;
    const int b  = bid >> 6;
    const int dt = (bid >> 3) & 7;
    const int sp = bid & 7;
    const int dbase = dt * 128;
    const int tid = threadIdx.x;
    const int td = tid & 15;   // d group: 8 contiguous d
    const int tk = tid >> 4;   // k group: 4 contiguous k

    __shared__ __align__(16) float xt[32][130]; // [s][d]
    __shared__ __align__(16) float ws[32][36];  // [s][k], row pad keeps 16B align

    unsigned long long acc[4][4]; // [kk][d-pair]
    #pragma unroll
    for (int i = 0; i < 4; i++)
        #pragma unroll
        for (int j = 0; j < 4; j++) acc[i][j] = 0ull;

    const float* w = out + OFF2 + (size_t)b * S_ * KK;

    for (int st = 0; st < 16; st++) {
        const int sb = sp * 512 + st * 32;
        __syncthreads();
        #pragma unroll
        for (int i = 0; i < 32; i++) {
            int idx = tid + i * 128;
            int d = idx & 127;
            int r = idx >> 7;
            xt[r][d] = x[((size_t)b * S_ + sb + r) * D_ + dbase + d];
        }
        #pragma unroll
        for (int i = 0; i < 8; i++) {
            int idx = tid + i * 128;
            int k = idx & 31;
            int r = idx >> 5;
            ws[r][k] = w[(size_t)(sb + r) * KK + k];
        }
        __syncthreads();

        #pragma unroll 4
        for (int r = 0; r < 32; r++) {
            float4 wv = *(const float4*)&ws[r][tk * 4];
            unsigned long long w0 = dup2(wv.x), w1 = dup2(wv.y),
                               w2 = dup2(wv.z), w3 = dup2(wv.w);
            #pragma unroll
            for (int dp = 0; dp < 4; dp++) {
                unsigned long long xv =
                    *(const unsigned long long*)&xt[r][td * 8 + dp * 2];
                acc[0][dp] = fma2(xv, w0, acc[0][dp]);
                acc[1][dp] = fma2(xv, w1, acc[1][dp]);
                acc[2][dp] = fma2(xv, w2, acc[2][dp]);
                acc[3][dp] = fma2(xv, w3, acc[3][dp]);
            }
        }
    }

    #pragma unroll
    for (int kk = 0; kk < 4; kk++) {
        int k = tk * 4 + kk;
        float* dst = &g_part[(((size_t)b * 8 + sp) * KK + k) * D_ + dbase + td * 8];
        #pragma unroll
        for (int dp = 0; dp < 4; dp++) {
            float2 v = unpack2(acc[kk][dp]);
            dst[dp * 2 + 0] = v.x;
            dst[dp * 2 + 1] = v.y;
        }
    }
}

// ---------------------------------------------------------------------------
// Phase D: reduce split-K partials into soft_slots + expert_inputs, and fill
// expert_weights (1/E) and expert_indices (e, value-cast to float).
// ---------------------------------------------------------------------------
__global__ void __launch_bounds__(256) phaseD(float* __restrict__ out) {
    const int i = blockIdx.x * 256 + threadIdx.x; // 262144 threads
    const int b = i >> 15;                        // / (KK*D)
    const int rem = i & 32767;
    float a = 0.f;
    #pragma unroll
    for (int sp = 0; sp < 8; sp++)
        a += g_part[((size_t)b * 8 + sp) * (KK * D_) + rem];
    out[OFF3 + i] = a;              // soft_slots [B,E,P,D]
    out[OFF4 + i] = a;              // expert_inputs [B,E,P*D] (same memory layout)
    out[OFF0 + i] = 0.125f;         // expert_weights = 1/E
    out[OFF1 + i] = (float)(i & 7); // expert_indices: [b,s,e] -> e
}

extern "C" void kernel_launch(void* const* d_in, const int* in_sizes, int n_in,
                              void* d_out, int out_size) {
    const float* x    = (const float*)d_in[0];
    const float* phiK = (const float*)d_in[1];
    const float* bias = (const float*)d_in[2];
    float* out = (float*)d_out;

    phaseA<<<256, 128>>>(x, phiK, bias);
    phaseB<<<256, 256>>>(out);
    phaseC<<<512, 128>>>(x, out);
    phaseD<<<1024, 256>>>(out);
}

// round 3
// speedup vs baseline: 2.2690x; 2.2690x over previous
#include <cuda_runtime.h>

// Problem constants
#define B_  8
#define S_  4096
#define D_  1024
#define KK  32      // E*P = 8*4

// Output layout: flat concat of (expert_weights, expert_indices, phi_weights,
// soft_slots, expert_inputs), all as float32.
#define OFF0 0              // expert_weights [B,S,E]      262144
#define OFF1 262144         // expert_indices [B,S,E]      262144
#define OFF2 524288         // phi_weights    [B,S,E,P]    1048576
#define OFF3 1572864        // soft_slots     [B,E,P,D]    262144
#define OFF4 1835008        // expert_inputs  [B,E,P*D]    262144

// Scratch (device globals: no allocation allowed)
__device__ float  g_L[B_ * KK * S_];        // logits, [b][k][s]   (4 MB)
__device__ float  g_part[B_ * 8 * KK * D_]; // split-K partials    (8 MB)
__device__ float2 g_ms[B_ * KK];            // per-(b,k) {max, inv_sum}

__device__ __forceinline__ unsigned long long fma2(unsigned long long a,
                                                   unsigned long long b,
                                                   unsigned long long c) {
    unsigned long long d;
    asm("fma.rn.f32x2 %0, %1, %2, %3;" : "=l"(d) : "l"(a), "l"(b), "l"(c));
    return d;
}
__device__ __forceinline__ unsigned long long dup2(float p) {
    unsigned long long d;
    asm("mov.b64 %0, {%1, %1};" : "=l"(d) : "f"(p));
    return d;
}
__device__ __forceinline__ float2 unpack2(unsigned long long v) {
    float2 r;
    asm("mov.b64 {%0, %1}, %2;" : "=f"(r.x), "=f"(r.y) : "l"(v));
    return r;
}

// ---------------------------------------------------------------------------
// Phase A: logits[b,k,s] = sum_d x[b,s,d] * phiK[d,k] + bias[k]
// Tile: 128 tokens x 32 k per block, 128 threads, thread = 8 tok x 4 k.
// Token pairs are STRIDED: pair index = tg + 16*i -> lanes hit consecutive
// word-pairs in smem (conflict-free LDS.64).
// ---------------------------------------------------------------------------
__global__ void __launch_bounds__(128) phaseA(const float* __restrict__ x,
                                              const float* __restrict__ phiK,
                                              const float* __restrict__ bias) {
    __shared__ __align__(16) float xs[32][130]; // [d][tok]
    __shared__ __align__(16) float ps[32][32];  // [d][k]

    const int tid  = threadIdx.x;
    const int tok0 = blockIdx.x * 128;          // never crosses a batch
    const int b    = tok0 / S_;
    const int s0   = tok0 - b * S_;
    const int tg   = tid & 15;                  // token-pair lane
    const int tk   = tid >> 4;                  // k group: 4 contiguous k

    unsigned long long acc[4][4];               // [kk][token-pair i]
    #pragma unroll
    for (int i = 0; i < 4; i++)
        #pragma unroll
        for (int j = 0; j < 4; j++) acc[i][j] = 0ull;

    for (int dt = 0; dt < 32; dt++) {
        const int dbase = dt * 32;
        __syncthreads();
        #pragma unroll
        for (int i = 0; i < 32; i++) {
            int idx = tid + i * 128;
            int d = idx & 31;
            int t = idx >> 5;
            xs[d][t] = x[(size_t)(tok0 + t) * D_ + dbase + d];
        }
        #pragma unroll
        for (int i = 0; i < 8; i++) {
            int idx = tid + i * 128;
            int d = idx >> 5;
            int k = idx & 31;
            ps[d][k] = phiK[(size_t)(dbase + d) * KK + k];
        }
        __syncthreads();

        #pragma unroll 8
        for (int d = 0; d < 32; d++) {
            float4 ph = *(const float4*)&ps[d][tk * 4];
            unsigned long long p0 = dup2(ph.x), p1 = dup2(ph.y),
                               p2 = dup2(ph.z), p3 = dup2(ph.w);
            #pragma unroll
            for (int i = 0; i < 4; i++) {
                unsigned long long xv =
                    *(const unsigned long long*)&xs[d][(tg + 16 * i) * 2];
                acc[0][i] = fma2(xv, p0, acc[0][i]);
                acc[1][i] = fma2(xv, p1, acc[1][i]);
                acc[2][i] = fma2(xv, p2, acc[2][i]);
                acc[3][i] = fma2(xv, p3, acc[3][i]);
            }
        }
    }

    // write logits to [b][k][s] scratch (float2, coalesced: lanes = consecutive pairs)
    #pragma unroll
    for (int kk = 0; kk < 4; kk++) {
        int k = tk * 4 + kk;
        float bv = bias[k];
        float* dst = &g_L[((size_t)b * KK + k) * S_ + s0];
        #pragma unroll
        for (int i = 0; i < 4; i++) {
            float2 v = unpack2(acc[kk][i]);
            v.x += bv; v.y += bv;
            *(float2*)&dst[(tg + 16 * i) * 2] = v;
        }
    }
}

// ---------------------------------------------------------------------------
// Phase B1: per-(b,k) softmax stats over S: max and 1/sum(exp).
// ---------------------------------------------------------------------------
__global__ void __launch_bounds__(256) phaseB1() {
    const int bk  = blockIdx.x;       // b*32 + k
    const int tid = threadIdx.x;
    const float* L = &g_L[(size_t)bk * S_];

    __shared__ float red[8];

    float v[16];
    float m = -1e30f;
    #pragma unroll
    for (int i = 0; i < 16; i++) {
        v[i] = L[tid + i * 256];
        m = fmaxf(m, v[i]);
    }
    #pragma unroll
    for (int o = 16; o > 0; o >>= 1) m = fmaxf(m, __shfl_xor_sync(0xffffffffu, m, o));
    if ((tid & 31) == 0) red[tid >> 5] = m;
    __syncthreads();
    if (tid < 32) {
        float t = (tid < 8) ? red[tid] : -1e30f;
        #pragma unroll
        for (int o = 4; o > 0; o >>= 1) t = fmaxf(t, __shfl_xor_sync(0xffffffffu, t, o));
        if (tid == 0) red[0] = t;
    }
    __syncthreads();
    m = red[0];
    __syncthreads();

    float s = 0.f;
    #pragma unroll
    for (int i = 0; i < 16; i++) s += __expf(v[i] - m);
    #pragma unroll
    for (int o = 16; o > 0; o >>= 1) s += __shfl_xor_sync(0xffffffffu, s, o);
    if ((tid & 31) == 0) red[tid >> 5] = s;
    __syncthreads();
    if (tid < 32) {
        float t = (tid < 8) ? red[tid] : 0.f;
        #pragma unroll
        for (int o = 4; o > 0; o >>= 1) t += __shfl_xor_sync(0xffffffffu, t, o);
        if (tid == 0) red[0] = t;
    }
    __syncthreads();
    if (tid == 0) {
        float2 r; r.x = m; r.y = 1.0f / red[0];
        g_ms[bk] = r;
    }
}

// ---------------------------------------------------------------------------
// Phase B2: normalize + transpose. Block = (b, 128-s tile). Reads g_L[k][s]
// coalesced, writes phi_weights [b][s][k] with STG.128 (k contiguous).
// ---------------------------------------------------------------------------
__global__ void __launch_bounds__(128) phaseB2(float* __restrict__ out) {
    const int bid = blockIdx.x;           // b*32 + stile
    const int b   = bid >> 5;
    const int s0  = (bid & 31) * 128;
    const int tid = threadIdx.x;

    __shared__ float  sm[32][129];        // pad 129 -> conflict-free both ways
    __shared__ float2 ms[32];

    if (tid < 32) ms[tid] = g_ms[b * KK + tid];
    __syncthreads();

    #pragma unroll
    for (int k = 0; k < 32; k++) {
        float v = g_L[((size_t)b * KK + k) * S_ + s0 + tid];
        sm[k][tid] = __expf(v - ms[k].x) * ms[k].y;
    }
    __syncthreads();

    float* dst = out + OFF2 + ((size_t)b * S_ + s0 + tid) * KK;
    #pragma unroll
    for (int k4 = 0; k4 < 8; k4++) {
        float4 v;
        v.x = sm[k4 * 4 + 0][tid];
        v.y = sm[k4 * 4 + 1][tid];
        v.z = sm[k4 * 4 + 2][tid];
        v.w = sm[k4 * 4 + 3][tid];
        *(float4*)&dst[k4 * 4] = v;
    }
}

// ---------------------------------------------------------------------------
// Phase C: partial[b,sp,k,d] = sum_{s in split sp} x[b,s,d] * w[b,s,k]
// Grid 512 = B x 8 d-tiles x 8 S-splits. Thread = 4 k x 8 d, d-pairs STRIDED
// (td + 16*dp) for conflict-free LDS.64.
// ---------------------------------------------------------------------------
__global__ void __launch_bounds__(128) phaseC(const float* __restrict__ x,
                                              const float* __restrict__ out) {
    const int bid = blockIdx.x;
    const int b  = bid >> 6;
    const int dt = (bid >> 3) & 7;
    const int sp = bid & 7;
    const int dbase = dt * 128;
    const int tid = threadIdx.x;
    const int td = tid & 15;   // d-pair lane
    const int tk = tid >> 4;   // k group: 4 contiguous k

    __shared__ __align__(16) float xt[32][130]; // [s][d]
    __shared__ __align__(16) float ws[32][36];  // [s][k]

    unsigned long long acc[4][4]; // [kk][d-pair i]
    #pragma unroll
    for (int i = 0; i < 4; i++)
        #pragma unroll
        for (int j = 0; j < 4; j++) acc[i][j] = 0ull;

    const float* w = out + OFF2 + (size_t)b * S_ * KK;

    for (int st = 0; st < 16; st++) {
        const int sb = sp * 512 + st * 32;
        __syncthreads();
        #pragma unroll
        for (int i = 0; i < 32; i++) {
            int idx = tid + i * 128;
            int d = idx & 127;
            int r = idx >> 7;
            xt[r][d] = x[((size_t)b * S_ + sb + r) * D_ + dbase + d];
        }
        #pragma unroll
        for (int i = 0; i < 8; i++) {
            int idx = tid + i * 128;
            int k = idx & 31;
            int r = idx >> 5;
            ws[r][k] = w[(size_t)(sb + r) * KK + k];
        }
        __syncthreads();

        #pragma unroll 8
        for (int r = 0; r < 32; r++) {
            float4 wv = *(const float4*)&ws[r][tk * 4];
            unsigned long long w0 = dup2(wv.x), w1 = dup2(wv.y),
                               w2 = dup2(wv.z), w3 = dup2(wv.w);
            #pragma unroll
            for (int i = 0; i < 4; i++) {
                unsigned long long xv =
                    *(const unsigned long long*)&xt[r][(td + 16 * i) * 2];
                acc[0][i] = fma2(xv, w0, acc[0][i]);
                acc[1][i] = fma2(xv, w1, acc[1][i]);
                acc[2][i] = fma2(xv, w2, acc[2][i]);
                acc[3][i] = fma2(xv, w3, acc[3][i]);
            }
        }
    }

    #pragma unroll
    for (int kk = 0; kk < 4; kk++) {
        int k = tk * 4 + kk;
        float* dst = &g_part[(((size_t)b * 8 + sp) * KK + k) * D_ + dbase];
        #pragma unroll
        for (int i = 0; i < 4; i++) {
            float2 v = unpack2(acc[kk][i]);
            *(float2*)&dst[(td + 16 * i) * 2] = v;
        }
    }
}

// ---------------------------------------------------------------------------
// Phase D: reduce split-K partials into soft_slots + expert_inputs, and fill
// expert_weights (1/E) and expert_indices (e, value-cast to float).
// ---------------------------------------------------------------------------
__global__ void __launch_bounds__(256) phaseD(float* __restrict__ out) {
    const int i = blockIdx.x * 256 + threadIdx.x; // 262144 threads
    const int b = i >> 15;                        // / (KK*D)
    const int rem = i & 32767;
    float a = 0.f;
    #pragma unroll
    for (int sp = 0; sp < 8; sp++)
        a += g_part[((size_t)b * 8 + sp) * (KK * D_) + rem];
    out[OFF3 + i] = a;              // soft_slots [B,E,P,D]
    out[OFF4 + i] = a;              // expert_inputs [B,E,P*D] (same layout)
    out[OFF0 + i] = 0.125f;         // expert_weights = 1/E
    out[OFF1 + i] = (float)(i & 7); // expert_indices: [b,s,e] -> e
}

extern "C" void kernel_launch(void* const* d_in, const int* in_sizes, int n_in,
                              void* d_out, int out_size) {
    const float* x    = (const float*)d_in[0];
    const float* phiK = (const float*)d_in[1];
    const float* bias = (const float*)d_in[2];
    float* out = (float*)d_out;

    phaseA<<<256, 128>>>(x, phiK, bias);
    phaseB1<<<256, 256>>>();
    phaseB2<<<256, 128>>>(out);
    phaseC<<<512, 128>>>(x, out);
    phaseD<<<1024, 256>>>(out);
}

// round 5
// speedup vs baseline: 2.5568x; 1.1268x over previous
#include <cuda_runtime.h>
#include <cstdint>

// Problem constants
#define B_  8
#define S_  4096
#define D_  1024
#define KK  32      // E*P = 8*4

// Output layout: flat concat of (expert_weights, expert_indices, phi_weights,
// soft_slots, expert_inputs), all as float32.
#define OFF0 0              // expert_weights [B,S,E]      262144
#define OFF1 262144         // expert_indices [B,S,E]      262144
#define OFF2 524288         // phi_weights    [B,S,E,P]    1048576
#define OFF3 1572864        // soft_slots     [B,E,P,D]    262144
#define OFF4 1835008        // expert_inputs  [B,E,P*D]    262144

#define NSPLIT 16           // S-splits in phaseC

// Scratch (device globals: no allocation allowed)
__device__ float  g_L [B_ * KK * S_];            // logits half0 / summed (4 MB)
__device__ float  g_L2[B_ * KK * S_];            // logits half1          (4 MB)
__device__ float  g_part[B_ * NSPLIT * KK * D_]; // split-K partials     (16 MB)
__device__ float2 g_ms[B_ * KK];                 // per-(b,k) {max, inv_sum}

__device__ __forceinline__ unsigned long long fma2(unsigned long long a,
                                                   unsigned long long b,
                                                   unsigned long long c) {
    unsigned long long d;
    asm("fma.rn.f32x2 %0, %1, %2, %3;" : "=l"(d) : "l"(a), "l"(b), "l"(c));
    return d;
}
__device__ __forceinline__ unsigned long long dup2(float p) {
    unsigned long long d;
    asm("mov.b64 %0, {%1, %1};" : "=l"(d) : "f"(p));
    return d;
}
__device__ __forceinline__ float2 unpack2(unsigned long long v) {
    float2 r;
    asm("mov.b64 {%0, %1}, %2;" : "=f"(r.x), "=f"(r.y) : "l"(v));
    return r;
}
__device__ __forceinline__ void cpa16(uint32_t dst, const float* src) {
    asm volatile("cp.async.cg.shared.global [%0], [%1], 16;" :: "r"(dst), "l"(src));
}
__device__ __forceinline__ void cpa_commit() {
    asm volatile("cp.async.commit_group;");
}

// ---------------------------------------------------------------------------
// Phase A: partial logits over half the D reduction.
// Grid 512: bid = tile*2 + half. Tile = 128 tokens x 32 k, 128 threads.
// half 0 -> g_L (with bias), half 1 -> g_L2.
// ---------------------------------------------------------------------------
__global__ void __launch_bounds__(128) phaseA(const float* __restrict__ x,
                                              const float* __restrict__ phiK,
                                              const float* __restrict__ bias) {
    __shared__ __align__(16) float xs[32][130]; // [d][tok]
    __shared__ __align__(16) float ps[32][32];  // [d][k]

    const int tid  = threadIdx.x;
    const int bid  = blockIdx.x;
    const int half = bid & 1;
    const int tile = bid >> 1;
    const int tok0 = tile * 128;                // never crosses a batch
    const int b    = tok0 / S_;
    const int s0   = tok0 - b * S_;
    const int tg   = tid & 15;                  // token-pair lane
    const int tk   = tid >> 4;                  // k group: 4 contiguous k

    unsigned long long acc[4][4];               // [kk][token-pair i]
    #pragma unroll
    for (int i = 0; i < 4; i++)
        #pragma unroll
        for (int j = 0; j < 4; j++) acc[i][j] = 0ull;

    for (int dt = 0; dt < 16; dt++) {
        const int dbase = (half * 16 + dt) * 32;
        __syncthreads();
        #pragma unroll
        for (int i = 0; i < 32; i++) {
            int idx = tid + i * 128;
            int d = idx & 31;
            int t = idx >> 5;
            xs[d][t] = x[(size_t)(tok0 + t) * D_ + dbase + d];
        }
        #pragma unroll
        for (int i = 0; i < 8; i++) {
            int idx = tid + i * 128;
            int d = idx >> 5;
            int k = idx & 31;
            ps[d][k] = phiK[(size_t)(dbase + d) * KK + k];
        }
        __syncthreads();

        #pragma unroll 8
        for (int d = 0; d < 32; d++) {
            float4 ph = *(const float4*)&ps[d][tk * 4];
            unsigned long long p0 = dup2(ph.x), p1 = dup2(ph.y),
                               p2 = dup2(ph.z), p3 = dup2(ph.w);
            #pragma unroll
            for (int i = 0; i < 4; i++) {
                unsigned long long xv =
                    *(const unsigned long long*)&xs[d][(tg + 16 * i) * 2];
                acc[0][i] = fma2(xv, p0, acc[0][i]);
                acc[1][i] = fma2(xv, p1, acc[1][i]);
                acc[2][i] = fma2(xv, p2, acc[2][i]);
                acc[3][i] = fma2(xv, p3, acc[3][i]);
            }
        }
    }

    float* Ldst = half ? g_L2 : g_L;
    #pragma unroll
    for (int kk = 0; kk < 4; kk++) {
        int k = tk * 4 + kk;
        float bv = half ? 0.f : bias[k];
        float* dst = &Ldst[((size_t)b * KK + k) * S_ + s0];
        #pragma unroll
        for (int i = 0; i < 4; i++) {
            float2 v = unpack2(acc[kk][i]);
            v.x += bv; v.y += bv;
            *(float2*)&dst[(tg + 16 * i) * 2] = v;
        }
    }
}

// ---------------------------------------------------------------------------
// Phase B1: sum the two logit halves (write back to g_L) and compute per-(b,k)
// softmax stats {max, 1/sum(exp)}.
// ---------------------------------------------------------------------------
__global__ void __launch_bounds__(256) phaseB1() {
    const int bk  = blockIdx.x;       // b*32 + k
    const int tid = threadIdx.x;
    float* L        = &g_L [(size_t)bk * S_];
    const float* L2 = &g_L2[(size_t)bk * S_];

    __shared__ float red[8];

    float v[16];
    float m = -1e30f;
    #pragma unroll
    for (int i = 0; i < 16; i++) {
        int idx = tid + i * 256;
        v[i] = L[idx] + L2[idx];
        L[idx] = v[i];
        m = fmaxf(m, v[i]);
    }
    #pragma unroll
    for (int o = 16; o > 0; o >>= 1) m = fmaxf(m, __shfl_xor_sync(0xffffffffu, m, o));
    if ((tid & 31) == 0) red[tid >> 5] = m;
    __syncthreads();
    if (tid < 32) {
        float t = (tid < 8) ? red[tid] : -1e30f;
        #pragma unroll
        for (int o = 4; o > 0; o >>= 1) t = fmaxf(t, __shfl_xor_sync(0xffffffffu, t, o));
        if (tid == 0) red[0] = t;
    }
    __syncthreads();
    m = red[0];
    __syncthreads();

    float s = 0.f;
    #pragma unroll
    for (int i = 0; i < 16; i++) s += __expf(v[i] - m);
    #pragma unroll
    for (int o = 16; o > 0; o >>= 1) s += __shfl_xor_sync(0xffffffffu, s, o);
    if ((tid & 31) == 0) red[tid >> 5] = s;
    __syncthreads();
    if (tid < 32) {
        float t = (tid < 8) ? red[tid] : 0.f;
        #pragma unroll
        for (int o = 4; o > 0; o >>= 1) t += __shfl_xor_sync(0xffffffffu, t, o);
        if (tid == 0) red[0] = t;
    }
    __syncthreads();
    if (tid == 0) {
        float2 r; r.x = m; r.y = 1.0f / red[0];
        g_ms[bk] = r;
    }
}

// ---------------------------------------------------------------------------
// Phase B2: normalize + transpose. Reads g_L[k][s] coalesced, writes
// phi_weights [b][s][k] with STG.128.
// ---------------------------------------------------------------------------
__global__ void __launch_bounds__(128) phaseB2(float* __restrict__ out) {
    const int bid = blockIdx.x;           // b*32 + stile
    const int b   = bid >> 5;
    const int s0  = (bid & 31) * 128;
    const int tid = threadIdx.x;

    __shared__ float  sm[32][129];
    __shared__ float2 ms[32];

    if (tid < 32) ms[tid] = g_ms[b * KK + tid];
    __syncthreads();

    #pragma unroll
    for (int k = 0; k < 32; k++) {
        float v = g_L[((size_t)b * KK + k) * S_ + s0 + tid];
        sm[k][tid] = __expf(v - ms[k].x) * ms[k].y;
    }
    __syncthreads();

    float* dst = out + OFF2 + ((size_t)b * S_ + s0 + tid) * KK;
    #pragma unroll
    for (int k4 = 0; k4 < 8; k4++) {
        float4 v;
        v.x = sm[k4 * 4 + 0][tid];
        v.y = sm[k4 * 4 + 1][tid];
        v.z = sm[k4 * 4 + 2][tid];
        v.w = sm[k4 * 4 + 3][tid];
        *(float4*)&dst[k4 * 4] = v;
    }
}

// ---------------------------------------------------------------------------
// Phase C: partial[b,sp,k,d] = sum_{s in split sp} x[b,s,d] * w[b,s,k]
// Grid 1024 = B x 8 d-tiles x 16 S-splits, 256 s per block (8 subtiles of 32),
// cp.async double-buffered x/w tiles. Thread = 4 k x 8 d (strided d-pairs).
// ---------------------------------------------------------------------------
__global__ void __launch_bounds__(128) phaseC(const float* __restrict__ x,
                                              const float* __restrict__ out) {
    const int bid = blockIdx.x;
    const int b   = bid >> 7;
    const int dt  = (bid >> 4) & 7;
    const int sp  = bid & 15;
    const int dbase = dt * 128;
    const int tid = threadIdx.x;
    const int td  = tid & 15;   // d-pair lane
    const int tk  = tid >> 4;   // k group: 4 contiguous k

    __shared__ __align__(16) float xt[2][32][132]; // [buf][s][d]
    __shared__ __align__(16) float ws[2][32][36];  // [buf][s][k]

    unsigned long long acc[4][4]; // [kk][d-pair i]
    #pragma unroll
    for (int i = 0; i < 4; i++)
        #pragma unroll
        for (int j = 0; j < 4; j++) acc[i][j] = 0ull;

    const float* w    = out + OFF2 + (size_t)b * S_ * KK;
    const float* xrow = x + (size_t)b * S_ * D_ + dbase;

    // async tile loader: subtile t -> buffer tb
    auto load_tile = [&](int tb, int t) {
        const int sb = sp * 256 + t * 32;
        #pragma unroll
        for (int j = 0; j < 8; j++) {          // x: 1024 16B chunks / 128 thr
            int chunk = tid + j * 128;
            int row = chunk >> 5;
            int c   = chunk & 31;
            cpa16((uint32_t)__cvta_generic_to_shared(&xt[tb][row][c * 4]),
                  xrow + (size_t)(sb + row) * D_ + c * 4);
        }
        #pragma unroll
        for (int j = 0; j < 2; j++) {          // w: 256 16B chunks / 128 thr
            int chunk = tid + j * 128;
            int row = chunk >> 3;
            int c   = chunk & 7;
            cpa16((uint32_t)__cvta_generic_to_shared(&ws[tb][row][c * 4]),
                  w + (size_t)(sb + row) * KK + c * 4);
        }
        cpa_commit();
    };

    load_tile(0, 0);

    #pragma unroll
    for (int t = 0; t < 8; t++) {
        if (t < 7) load_tile((t + 1) & 1, t + 1);
        if (t < 7) asm volatile("cp.async.wait_group 1;" ::: "memory");
        else       asm volatile("cp.async.wait_group 0;" ::: "memory");
        __syncthreads();

        const int tb = t & 1;
        #pragma unroll 8
        for (int r = 0; r < 32; r++) {
            float4 wv = *(const float4*)&ws[tb][r][tk * 4];
            unsigned long long w0 = dup2(wv.x), w1 = dup2(wv.y),
                               w2 = dup2(wv.z), w3 = dup2(wv.w);
            #pragma unroll
            for (int i = 0; i < 4; i++) {
                unsigned long long xv =
                    *(const unsigned long long*)&xt[tb][r][(td + 16 * i) * 2];
                acc[0][i] = fma2(xv, w0, acc[0][i]);
                acc[1][i] = fma2(xv, w1, acc[1][i]);
                acc[2][i] = fma2(xv, w2, acc[2][i]);
                acc[3][i] = fma2(xv, w3, acc[3][i]);
            }
        }
        __syncthreads();
    }

    #pragma unroll
    for (int kk = 0; kk < 4; kk++) {
        int k = tk * 4 + kk;
        float* dst = &g_part[(((size_t)b * NSPLIT + sp) * KK + k) * D_ + dbase];
        #pragma unroll
        for (int i = 0; i < 4; i++) {
            float2 v = unpack2(acc[kk][i]);
            *(float2*)&dst[(td + 16 * i) * 2] = v;
        }
    }
}

// ---------------------------------------------------------------------------
// Phase D: reduce split-K partials into soft_slots + expert_inputs, and fill
// expert_weights (1/E) and expert_indices (e, value-cast to float).
// ---------------------------------------------------------------------------
__global__ void __launch_bounds__(256) phaseD(float* __restrict__ out) {
    const int i = blockIdx.x * 256 + threadIdx.x; // 262144 threads
    const int b = i >> 15;                        // / (KK*D)
    const int rem = i & 32767;
    float a = 0.f;
    #pragma unroll
    for (int sp = 0; sp < NSPLIT; sp++)
        a += g_part[((size_t)b * NSPLIT + sp) * (KK * D_) + rem];
    out[OFF3 + i] = a;              // soft_slots [B,E,P,D]
    out[OFF4 + i] = a;              // expert_inputs [B,E,P*D] (same layout)
    out[OFF0 + i] = 0.125f;         // expert_weights = 1/E
    out[OFF1 + i] = (float)(i & 7); // expert_indices: [b,s,e] -> e
}

extern "C" void kernel_launch(void* const* d_in, const int* in_sizes, int n_in,
                              void* d_out, int out_size) {
    const float* x    = (const float*)d_in[0];
    const float* phiK = (const float*)d_in[1];
    const float* bias = (const float*)d_in[2];
    float* out = (float*)d_out;

    phaseA<<<512, 128>>>(x, phiK, bias);
    phaseB1<<<256, 256>>>();
    phaseB2<<<256, 128>>>(out);
    phaseC<<<1024, 128>>>(x, out);
    phaseD<<<1024, 256>>>(out);
}

// round 6
// speedup vs baseline: 2.7945x; 1.0930x over previous
#include <cuda_runtime.h>
#include <cstdint>

// Problem constants
#define B_  8
#define S_  4096
#define D_  1024
#define KK  32      // E*P = 8*4

// Output layout: flat concat of (expert_weights, expert_indices, phi_weights,
// soft_slots, expert_inputs), all as float32.
#define OFF0 0              // expert_weights [B,S,E]      262144
#define OFF1 262144         // expert_indices [B,S,E]      262144
#define OFF2 524288         // phi_weights    [B,S,E,P]    1048576
#define OFF3 1572864        // soft_slots     [B,E,P,D]    262144
#define OFF4 1835008        // expert_inputs  [B,E,P*D]    262144

#define NSPLIT 16           // S-splits in phaseC
#define NHALF  4            // D-splits in phaseA

// Scratch (device globals: no allocation allowed)
__device__ float  g_Lh[NHALF][B_ * KK * S_];     // logit partials (16 MB); [0] holds sum
__device__ float  g_part[B_ * NSPLIT * KK * D_]; // split-K partials (16 MB)
__device__ float2 g_ms[B_ * KK];                 // per-(b,k) {max, inv_sum}

__device__ __forceinline__ unsigned long long fma2(unsigned long long a,
                                                   unsigned long long b,
                                                   unsigned long long c) {
    unsigned long long d;
    asm("fma.rn.f32x2 %0, %1, %2, %3;" : "=l"(d) : "l"(a), "l"(b), "l"(c));
    return d;
}
__device__ __forceinline__ unsigned long long dup2(float p) {
    unsigned long long d;
    asm("mov.b64 %0, {%1, %1};" : "=l"(d) : "f"(p));
    return d;
}
__device__ __forceinline__ float2 unpack2(unsigned long long v) {
    float2 r;
    asm("mov.b64 {%0, %1}, %2;" : "=f"(r.x), "=f"(r.y) : "l"(v));
    return r;
}
__device__ __forceinline__ void cpa16(uint32_t dst, const float* src) {
    asm volatile("cp.async.cg.shared.global [%0], [%1], 16;" :: "r"(dst), "l"(src));
}
__device__ __forceinline__ void cpa_commit() {
    asm volatile("cp.async.commit_group;");
}

// ---------------------------------------------------------------------------
// Phase A: partial logits over a quarter of the D reduction.
// Grid 1024: bid = tile*4 + half. Tile = 128 tokens x 32 k, 128 threads.
// ~21 KB smem -> ~7 CTAs/SM: entire phase is one resident wave.
// ---------------------------------------------------------------------------
__global__ void __launch_bounds__(128) phaseA(const float* __restrict__ x,
                                              const float* __restrict__ phiK,
                                              const float* __restrict__ bias) {
    __shared__ __align__(16) float xs[32][130]; // [d][tok]
    __shared__ __align__(16) float ps[32][32];  // [d][k]

    const int tid  = threadIdx.x;
    const int bid  = blockIdx.x;
    const int half = bid & 3;
    const int tile = bid >> 2;
    const int tok0 = tile * 128;                // never crosses a batch
    const int b    = tok0 / S_;
    const int s0   = tok0 - b * S_;
    const int tg   = tid & 15;                  // token-pair lane
    const int tk   = tid >> 4;                  // k group: 4 contiguous k

    unsigned long long acc[4][4];               // [kk][token-pair i]
    #pragma unroll
    for (int i = 0; i < 4; i++)
        #pragma unroll
        for (int j = 0; j < 4; j++) acc[i][j] = 0ull;

    for (int dt = 0; dt < 8; dt++) {
        const int dbase = half * 256 + dt * 32;
        __syncthreads();
        #pragma unroll
        for (int i = 0; i < 32; i++) {
            int idx = tid + i * 128;
            int d = idx & 31;
            int t = idx >> 5;
            xs[d][t] = x[(size_t)(tok0 + t) * D_ + dbase + d];
        }
        #pragma unroll
        for (int i = 0; i < 8; i++) {
            int idx = tid + i * 128;
            int d = idx >> 5;
            int k = idx & 31;
            ps[d][k] = phiK[(size_t)(dbase + d) * KK + k];
        }
        __syncthreads();

        #pragma unroll 8
        for (int d = 0; d < 32; d++) {
            float4 ph = *(const float4*)&ps[d][tk * 4];
            unsigned long long p0 = dup2(ph.x), p1 = dup2(ph.y),
                               p2 = dup2(ph.z), p3 = dup2(ph.w);
            #pragma unroll
            for (int i = 0; i < 4; i++) {
                unsigned long long xv =
                    *(const unsigned long long*)&xs[d][(tg + 16 * i) * 2];
                acc[0][i] = fma2(xv, p0, acc[0][i]);
                acc[1][i] = fma2(xv, p1, acc[1][i]);
                acc[2][i] = fma2(xv, p2, acc[2][i]);
                acc[3][i] = fma2(xv, p3, acc[3][i]);
            }
        }
    }

    float* Ldst = g_Lh[half];
    #pragma unroll
    for (int kk = 0; kk < 4; kk++) {
        int k = tk * 4 + kk;
        float bv = (half == 0) ? bias[k] : 0.f;
        float* dst = &Ldst[((size_t)b * KK + k) * S_ + s0];
        #pragma unroll
        for (int i = 0; i < 4; i++) {
            float2 v = unpack2(acc[kk][i]);
            v.x += bv; v.y += bv;
            *(float2*)&dst[(tg + 16 * i) * 2] = v;
        }
    }
}

// ---------------------------------------------------------------------------
// Phase B1: sum the 4 logit partials (write back to g_Lh[0]) and compute
// per-(b,k) softmax stats {max, 1/sum(exp)}. float4 loads.
// ---------------------------------------------------------------------------
__global__ void __launch_bounds__(256) phaseB1() {
    const int bk  = blockIdx.x;       // b*32 + k
    const int tid = threadIdx.x;
    const size_t base4 = (size_t)bk * (S_ / 4);
    float4* L0       = (float4*)g_Lh[0] + base4;
    const float4* L1 = (const float4*)g_Lh[1] + base4;
    const float4* L2 = (const float4*)g_Lh[2] + base4;
    const float4* L3 = (const float4*)g_Lh[3] + base4;

    __shared__ float red[8];

    float4 v[4];
    float m = -1e30f;
    #pragma unroll
    for (int i = 0; i < 4; i++) {
        int idx = tid + i * 256;
        float4 a = L0[idx], b4 = L1[idx], c = L2[idx], d = L3[idx];
        a.x += b4.x + c.x + d.x;
        a.y += b4.y + c.y + d.y;
        a.z += b4.z + c.z + d.z;
        a.w += b4.w + c.w + d.w;
        v[i] = a;
        L0[idx] = a;
        m = fmaxf(m, fmaxf(fmaxf(a.x, a.y), fmaxf(a.z, a.w)));
    }
    #pragma unroll
    for (int o = 16; o > 0; o >>= 1) m = fmaxf(m, __shfl_xor_sync(0xffffffffu, m, o));
    if ((tid & 31) == 0) red[tid >> 5] = m;
    __syncthreads();
    if (tid < 32) {
        float t = (tid < 8) ? red[tid] : -1e30f;
        #pragma unroll
        for (int o = 4; o > 0; o >>= 1) t = fmaxf(t, __shfl_xor_sync(0xffffffffu, t, o));
        if (tid == 0) red[0] = t;
    }
    __syncthreads();
    m = red[0];
    __syncthreads();

    float s = 0.f;
    #pragma unroll
    for (int i = 0; i < 4; i++) {
        s += __expf(v[i].x - m) + __expf(v[i].y - m)
           + __expf(v[i].z - m) + __expf(v[i].w - m);
    }
    #pragma unroll
    for (int o = 16; o > 0; o >>= 1) s += __shfl_xor_sync(0xffffffffu, s, o);
    if ((tid & 31) == 0) red[tid >> 5] = s;
    __syncthreads();
    if (tid < 32) {
        float t = (tid < 8) ? red[tid] : 0.f;
        #pragma unroll
        for (int o = 4; o > 0; o >>= 1) t += __shfl_xor_sync(0xffffffffu, t, o);
        if (tid == 0) red[0] = t;
    }
    __syncthreads();
    if (tid == 0) {
        float2 r; r.x = m; r.y = 1.0f / red[0];
        g_ms[bk] = r;
    }
}

// ---------------------------------------------------------------------------
// Phase B2: normalize + transpose. Reads g_Lh[0][k][s] coalesced, writes
// phi_weights [b][s][k] with STG.128.
// ---------------------------------------------------------------------------
__global__ void __launch_bounds__(128) phaseB2(float* __restrict__ out) {
    const int bid = blockIdx.x;           // b*32 + stile
    const int b   = bid >> 5;
    const int s0  = (bid & 31) * 128;
    const int tid = threadIdx.x;

    __shared__ float  sm[32][129];
    __shared__ float2 ms[32];

    if (tid < 32) ms[tid] = g_ms[b * KK + tid];
    __syncthreads();

    #pragma unroll
    for (int k = 0; k < 32; k++) {
        float v = g_Lh[0][((size_t)b * KK + k) * S_ + s0 + tid];
        sm[k][tid] = __expf(v - ms[k].x) * ms[k].y;
    }
    __syncthreads();

    float* dst = out + OFF2 + ((size_t)b * S_ + s0 + tid) * KK;
    #pragma unroll
    for (int k4 = 0; k4 < 8; k4++) {
        float4 v;
        v.x = sm[k4 * 4 + 0][tid];
        v.y = sm[k4 * 4 + 1][tid];
        v.z = sm[k4 * 4 + 2][tid];
        v.w = sm[k4 * 4 + 3][tid];
        *(float4*)&dst[k4 * 4] = v;
    }
}

// ---------------------------------------------------------------------------
// Phase C: partial[b,sp,k,d] = sum_{s in split sp} x[b,s,d] * w[b,s,k]
// Grid 1024 = B x 8 d-tiles x 16 S-splits, 256 s per block (8 subtiles of 32),
// cp.async double-buffered x/w tiles. Thread = 4 k x 8 d (strided d-pairs).
// ---------------------------------------------------------------------------
__global__ void __launch_bounds__(128) phaseC(const float* __restrict__ x,
                                              const float* __restrict__ out) {
    const int bid = blockIdx.x;
    const int b   = bid >> 7;
    const int dt  = (bid >> 4) & 7;
    const int sp  = bid & 15;
    const int dbase = dt * 128;
    const int tid = threadIdx.x;
    const int td  = tid & 15;   // d-pair lane
    const int tk  = tid >> 4;   // k group: 4 contiguous k

    __shared__ __align__(16) float xt[2][32][132]; // [buf][s][d]
    __shared__ __align__(16) float ws[2][32][36];  // [buf][s][k]

    unsigned long long acc[4][4]; // [kk][d-pair i]
    #pragma unroll
    for (int i = 0; i < 4; i++)
        #pragma unroll
        for (int j = 0; j < 4; j++) acc[i][j] = 0ull;

    const float* w    = out + OFF2 + (size_t)b * S_ * KK;
    const float* xrow = x + (size_t)b * S_ * D_ + dbase;

    auto load_tile = [&](int tb, int t) {
        const int sb = sp * 256 + t * 32;
        #pragma unroll
        for (int j = 0; j < 8; j++) {          // x: 1024 16B chunks / 128 thr
            int chunk = tid + j * 128;
            int row = chunk >> 5;
            int c   = chunk & 31;
            cpa16((uint32_t)__cvta_generic_to_shared(&xt[tb][row][c * 4]),
                  xrow + (size_t)(sb + row) * D_ + c * 4);
        }
        #pragma unroll
        for (int j = 0; j < 2; j++) {          // w: 256 16B chunks / 128 thr
            int chunk = tid + j * 128;
            int row = chunk >> 3;
            int c   = chunk & 7;
            cpa16((uint32_t)__cvta_generic_to_shared(&ws[tb][row][c * 4]),
                  w + (size_t)(sb + row) * KK + c * 4);
        }
        cpa_commit();
    };

    load_tile(0, 0);

    #pragma unroll
    for (int t = 0; t < 8; t++) {
        if (t < 7) load_tile((t + 1) & 1, t + 1);
        if (t < 7) asm volatile("cp.async.wait_group 1;" ::: "memory");
        else       asm volatile("cp.async.wait_group 0;" ::: "memory");
        __syncthreads();

        const int tb = t & 1;
        #pragma unroll 8
        for (int r = 0; r < 32; r++) {
            float4 wv = *(const float4*)&ws[tb][r][tk * 4];
            unsigned long long w0 = dup2(wv.x), w1 = dup2(wv.y),
                               w2 = dup2(wv.z), w3 = dup2(wv.w);
            #pragma unroll
            for (int i = 0; i < 4; i++) {
                unsigned long long xv =
                    *(const unsigned long long*)&xt[tb][r][(td + 16 * i) * 2];
                acc[0][i] = fma2(xv, w0, acc[0][i]);
                acc[1][i] = fma2(xv, w1, acc[1][i]);
                acc[2][i] = fma2(xv, w2, acc[2][i]);
                acc[3][i] = fma2(xv, w3, acc[3][i]);
            }
        }
        __syncthreads();
    }

    #pragma unroll
    for (int kk = 0; kk < 4; kk++) {
        int k = tk * 4 + kk;
        float* dst = &g_part[(((size_t)b * NSPLIT + sp) * KK + k) * D_ + dbase];
        #pragma unroll
        for (int i = 0; i < 4; i++) {
            float2 v = unpack2(acc[kk][i]);
            *(float2*)&dst[(td + 16 * i) * 2] = v;
        }
    }
}

// ---------------------------------------------------------------------------
// Phase D: reduce split-K partials into soft_slots + expert_inputs, and fill
// expert_weights (1/E) and expert_indices. Fully float4.
// ---------------------------------------------------------------------------
__global__ void __launch_bounds__(256) phaseD(float* __restrict__ out) {
    const int i4 = blockIdx.x * 256 + threadIdx.x; // 65536 float4 threads
    const int b  = i4 >> 13;                       // / (KK*D/4)
    const int rem4 = i4 & 8191;

    const float4* part4 = (const float4*)g_part;
    float4 a = make_float4(0.f, 0.f, 0.f, 0.f);
    #pragma unroll
    for (int sp = 0; sp < NSPLIT; sp++) {
        float4 p = part4[((size_t)b * NSPLIT + sp) * (KK * D_ / 4) + rem4];
        a.x += p.x; a.y += p.y; a.z += p.z; a.w += p.w;
    }
    float4* out4 = (float4*)out;
    out4[OFF3 / 4 + i4] = a;        // soft_slots [B,E,P,D]
    out4[OFF4 / 4 + i4] = a;        // expert_inputs [B,E,P*D] (same layout)
    out4[OFF0 / 4 + i4] = make_float4(0.125f, 0.125f, 0.125f, 0.125f);
    // expert_indices: [b,s,e] -> e; element index = 4*i4 + {0..3}, pattern mod 8
    float e0 = (float)((4 * i4) & 7);
    out4[OFF1 / 4 + i4] = make_float4(e0, e0 + 1.f, e0 + 2.f, e0 + 3.f);
}

extern "C" void kernel_launch(void* const* d_in, const int* in_sizes, int n_in,
                              void* d_out, int out_size) {
    const float* x    = (const float*)d_in[0];
    const float* phiK = (const float*)d_in[1];
    const float* bias = (const float*)d_in[2];
    float* out = (float*)d_out;

    phaseA<<<1024, 128>>>(x, phiK, bias);
    phaseB1<<<256, 256>>>();
    phaseB2<<<256, 128>>>(out);
    phaseC<<<1024, 128>>>(x, out);
    phaseD<<<256, 256>>>(out);
}

// round 7
// speedup vs baseline: 2.8529x; 1.0209x over previous
#include <cuda_runtime.h>
#include <cstdint>

// Problem constants
#define B_  8
#define S_  4096
#define D_  1024
#define KK  32      // E*P = 8*4

// Output layout: flat concat of (expert_weights, expert_indices, phi_weights,
// soft_slots, expert_inputs), all as float32.
#define OFF0 0              // expert_weights [B,S,E]      262144
#define OFF1 262144         // expert_indices [B,S,E]      262144
#define OFF2 524288         // phi_weights    [B,S,E,P]    1048576
#define OFF3 1572864        // soft_slots     [B,E,P,D]    262144
#define OFF4 1835008        // expert_inputs  [B,E,P*D]    262144

#define NSPLIT 16           // S-splits in phaseC
#define NHALF  4            // D-splits in phaseA

// Scratch (device globals: no allocation allowed)
__device__ float  g_Lh[NHALF][B_ * KK * S_];     // logit partials (16 MB); [0] holds sum
__device__ float  g_part[B_ * NSPLIT * KK * D_]; // split-K partials (16 MB)
__device__ float2 g_wd[B_ * S_ * KK];            // duplicated weights (8 MB)
__device__ float2 g_ms[B_ * KK];                 // per-(b,k) {max, inv_sum}

__device__ __forceinline__ unsigned long long fma2(unsigned long long a,
                                                   unsigned long long b,
                                                   unsigned long long c) {
    unsigned long long d;
    asm("fma.rn.f32x2 %0, %1, %2, %3;" : "=l"(d) : "l"(a), "l"(b), "l"(c));
    return d;
}
__device__ __forceinline__ unsigned long long dup2(float p) {
    unsigned long long d;
    asm("mov.b64 %0, {%1, %1};" : "=l"(d) : "f"(p));
    return d;
}
__device__ __forceinline__ float2 unpack2(unsigned long long v) {
    float2 r;
    asm("mov.b64 {%0, %1}, %2;" : "=f"(r.x), "=f"(r.y) : "l"(v));
    return r;
}
__device__ __forceinline__ void cpa16(uint32_t dst, const void* src) {
    asm volatile("cp.async.cg.shared.global [%0], [%1], 16;" :: "r"(dst), "l"(src));
}
__device__ __forceinline__ void cpa_commit() {
    asm volatile("cp.async.commit_group;");
}

// ---------------------------------------------------------------------------
// Phase A: partial logits over a quarter of D, cp.async double-buffered.
// Grid 1024: bid = tile*4 + half. Tile = 128 tokens x 32 k.
// f32x2 pairs over k: x stays in natural [tok][d] layout (cp.async direct),
// x scalar broadcast per 4-lane k-group, phi pairs via LDS.64.
// Thread: kt = tid&3 (8 k = 4 pairs), tokt = tid>>2 (4 tokens, stride 32).
// ---------------------------------------------------------------------------
__global__ void __launch_bounds__(128) phaseA(const float* __restrict__ x,
                                              const float* __restrict__ phiK,
                                              const float* __restrict__ bias) {
    __shared__ __align__(16) float xs[2][128][36]; // [buf][tok][d] (+pad, 16B-aligned rows)
    __shared__ __align__(16) float ps[2][32][32];  // [buf][d][k]

    const int tid  = threadIdx.x;
    const int bid  = blockIdx.x;
    const int half = bid & 3;
    const int tile = bid >> 2;
    const int tok0 = tile * 128;                // never crosses a batch
    const int b    = tok0 / S_;
    const int s0   = tok0 - b * S_;
    const int kt   = tid & 3;                   // k-group: 8 k = 4 pairs
    const int tokt = tid >> 2;                  // token lane: 4 tokens stride 32

    unsigned long long acc[4][4];               // [token i][k-pair j]
    #pragma unroll
    for (int i = 0; i < 4; i++)
        #pragma unroll
        for (int j = 0; j < 4; j++) acc[i][j] = 0ull;

    const float* xbase = x + (size_t)tok0 * D_ + half * 256;

    auto load_tile = [&](int tb, int dt) {
        const int dbase = dt * 32;
        #pragma unroll
        for (int j = 0; j < 8; j++) {           // x: 128 tok x 32 d = 1024 chunks
            int chunk = tid + j * 128;
            int row = chunk >> 3;
            int c   = chunk & 7;
            cpa16((uint32_t)__cvta_generic_to_shared(&xs[tb][row][c * 4]),
                  xbase + (size_t)row * D_ + dbase + c * 4);
        }
        #pragma unroll
        for (int j = 0; j < 2; j++) {           // phi: 32 d x 32 k = 256 chunks
            int chunk = tid + j * 128;
            int d = chunk >> 3;
            int c = chunk & 7;
            cpa16((uint32_t)__cvta_generic_to_shared(&ps[tb][d][c * 4]),
                  phiK + (size_t)(half * 256 + dbase + d) * KK + c * 4);
        }
        cpa_commit();
    };

    load_tile(0, 0);

    #pragma unroll
    for (int t = 0; t < 8; t++) {
        if (t < 7) load_tile((t + 1) & 1, t + 1);
        if (t < 7) asm volatile("cp.async.wait_group 1;" ::: "memory");
        else       asm volatile("cp.async.wait_group 0;" ::: "memory");
        __syncthreads();

        const int tb = t & 1;
        #pragma unroll 8
        for (int d = 0; d < 32; d++) {
            unsigned long long p0 = *(const unsigned long long*)&ps[tb][d][kt * 8 + 0];
            unsigned long long p1 = *(const unsigned long long*)&ps[tb][d][kt * 8 + 2];
            unsigned long long p2 = *(const unsigned long long*)&ps[tb][d][kt * 8 + 4];
            unsigned long long p3 = *(const unsigned long long*)&ps[tb][d][kt * 8 + 6];
            #pragma unroll
            for (int i = 0; i < 4; i++) {
                unsigned long long xv = dup2(xs[tb][tokt + 32 * i][d]);
                acc[i][0] = fma2(xv, p0, acc[i][0]);
                acc[i][1] = fma2(xv, p1, acc[i][1]);
                acc[i][2] = fma2(xv, p2, acc[i][2]);
                acc[i][3] = fma2(xv, p3, acc[i][3]);
            }
        }
        __syncthreads();
    }

    // bias (only half 0 carries it)
    float bv[8];
    #pragma unroll
    for (int j = 0; j < 8; j++)
        bv[j] = (half == 0) ? bias[kt * 8 + j] : 0.f;

    float* Ldst = g_Lh[half] + (size_t)b * KK * S_ + s0;
    #pragma unroll
    for (int i = 0; i < 4; i++) {
        int tok = tokt + 32 * i;
        #pragma unroll
        for (int j = 0; j < 4; j++) {
            float2 v = unpack2(acc[i][j]);
            int k0 = kt * 8 + 2 * j;
            Ldst[(size_t)k0 * S_ + tok]       = v.x + bv[2 * j];
            Ldst[(size_t)(k0 + 1) * S_ + tok] = v.y + bv[2 * j + 1];
        }
    }
}

// ---------------------------------------------------------------------------
// Phase B1: sum the 4 logit partials (write back to g_Lh[0]) and compute
// per-(b,k) softmax stats {max, 1/sum(exp)}. float4 loads.
// ---------------------------------------------------------------------------
__global__ void __launch_bounds__(256) phaseB1() {
    const int bk  = blockIdx.x;       // b*32 + k
    const int tid = threadIdx.x;
    const size_t base4 = (size_t)bk * (S_ / 4);
    float4* L0       = (float4*)g_Lh[0] + base4;
    const float4* L1 = (const float4*)g_Lh[1] + base4;
    const float4* L2 = (const float4*)g_Lh[2] + base4;
    const float4* L3 = (const float4*)g_Lh[3] + base4;

    __shared__ float red[8];

    float4 v[4];
    float m = -1e30f;
    #pragma unroll
    for (int i = 0; i < 4; i++) {
        int idx = tid + i * 256;
        float4 a = L0[idx], b4 = L1[idx], c = L2[idx], d = L3[idx];
        a.x += b4.x + c.x + d.x;
        a.y += b4.y + c.y + d.y;
        a.z += b4.z + c.z + d.z;
        a.w += b4.w + c.w + d.w;
        v[i] = a;
        L0[idx] = a;
        m = fmaxf(m, fmaxf(fmaxf(a.x, a.y), fmaxf(a.z, a.w)));
    }
    #pragma unroll
    for (int o = 16; o > 0; o >>= 1) m = fmaxf(m, __shfl_xor_sync(0xffffffffu, m, o));
    if ((tid & 31) == 0) red[tid >> 5] = m;
    __syncthreads();
    if (tid < 32) {
        float t = (tid < 8) ? red[tid] : -1e30f;
        #pragma unroll
        for (int o = 4; o > 0; o >>= 1) t = fmaxf(t, __shfl_xor_sync(0xffffffffu, t, o));
        if (tid == 0) red[0] = t;
    }
    __syncthreads();
    m = red[0];
    __syncthreads();

    float s = 0.f;
    #pragma unroll
    for (int i = 0; i < 4; i++) {
        s += __expf(v[i].x - m) + __expf(v[i].y - m)
           + __expf(v[i].z - m) + __expf(v[i].w - m);
    }
    #pragma unroll
    for (int o = 16; o > 0; o >>= 1) s += __shfl_xor_sync(0xffffffffu, s, o);
    if ((tid & 31) == 0) red[tid >> 5] = s;
    __syncthreads();
    if (tid < 32) {
        float t = (tid < 8) ? red[tid] : 0.f;
        #pragma unroll
        for (int o = 4; o > 0; o >>= 1) t += __shfl_xor_sync(0xffffffffu, t, o);
        if (tid == 0) red[0] = t;
    }
    __syncthreads();
    if (tid == 0) {
        float2 r; r.x = m; r.y = 1.0f / red[0];
        g_ms[bk] = r;
    }
}

// ---------------------------------------------------------------------------
// Phase B2: normalize + transpose. Writes phi_weights [b][s][k] (STG.128)
// AND the duplicated-weight scratch g_wd[b][s][k] = (w,w) for phaseC.
// ---------------------------------------------------------------------------
__global__ void __launch_bounds__(128) phaseB2(float* __restrict__ out) {
    const int bid = blockIdx.x;           // b*32 + stile
    const int b   = bid >> 5;
    const int s0  = (bid & 31) * 128;
    const int tid = threadIdx.x;
    const int wrp = tid >> 5;
    const int ln  = tid & 31;

    __shared__ float  sm[32][129];
    __shared__ float2 ms[32];

    if (tid < 32) ms[tid] = g_ms[b * KK + tid];
    __syncthreads();

    #pragma unroll
    for (int k = 0; k < 32; k++) {
        float v = g_Lh[0][((size_t)b * KK + k) * S_ + s0 + tid];
        sm[k][tid] = __expf(v - ms[k].x) * ms[k].y;
    }
    __syncthreads();

    // phi_weights output, [s][k] with k contiguous
    float* dst = out + OFF2 + ((size_t)b * S_ + s0 + tid) * KK;
    #pragma unroll
    for (int k4 = 0; k4 < 8; k4++) {
        float4 v;
        v.x = sm[k4 * 4 + 0][tid];
        v.y = sm[k4 * 4 + 1][tid];
        v.z = sm[k4 * 4 + 2][tid];
        v.w = sm[k4 * 4 + 3][tid];
        *(float4*)&dst[k4 * 4] = v;
    }

    // duplicated weights: warp per s-row, lane = k -> fully coalesced float2
    #pragma unroll
    for (int rr = 0; rr < 32; rr++) {
        int s = wrp * 32 + rr;
        float v = sm[ln][s];
        g_wd[((size_t)b * S_ + s0 + s) * KK + ln] = make_float2(v, v);
    }
}

// ---------------------------------------------------------------------------
// Phase C: partial[b,sp,k,d] = sum_{s in split sp} x[b,s,d] * w[b,s,k]
// cp.async double-buffered; w comes pre-duplicated from g_wd -> inner loop
// has zero MOVs: 8 LDS.64 + 16 FFMA2 per r.
// ---------------------------------------------------------------------------
__global__ void __launch_bounds__(128) phaseC(const float* __restrict__ x) {
    const int bid = blockIdx.x;
    const int b   = bid >> 7;
    const int dt  = (bid >> 4) & 7;
    const int sp  = bid & 15;
    const int dbase = dt * 128;
    const int tid = threadIdx.x;
    const int td  = tid & 15;   // d-pair lane
    const int tk  = tid >> 4;   // k group: 4 contiguous k

    __shared__ __align__(16) float  xt[2][32][132]; // [buf][s][d]
    __shared__ __align__(16) float2 ws[2][32][32];  // [buf][s][k] duplicated pairs

    unsigned long long acc[4][4]; // [kk][d-pair i]
    #pragma unroll
    for (int i = 0; i < 4; i++)
        #pragma unroll
        for (int j = 0; j < 4; j++) acc[i][j] = 0ull;

    const float2* w   = g_wd + (size_t)b * S_ * KK;
    const float* xrow = x + (size_t)b * S_ * D_ + dbase;

    auto load_tile = [&](int tb, int t) {
        const int sb = sp * 256 + t * 32;
        #pragma unroll
        for (int j = 0; j < 8; j++) {          // x: 1024 16B chunks / 128 thr
            int chunk = tid + j * 128;
            int row = chunk >> 5;
            int c   = chunk & 31;
            cpa16((uint32_t)__cvta_generic_to_shared(&xt[tb][row][c * 4]),
                  xrow + (size_t)(sb + row) * D_ + c * 4);
        }
        #pragma unroll
        for (int j = 0; j < 4; j++) {          // w: 32 rows x 256 B = 512 chunks
            int chunk = tid + j * 128;
            int row = chunk >> 4;
            int c   = chunk & 15;
            cpa16((uint32_t)__cvta_generic_to_shared(&ws[tb][row][c * 2]),
                  w + (size_t)(sb + row) * KK + c * 2);
        }
        cpa_commit();
    };

    load_tile(0, 0);

    #pragma unroll
    for (int t = 0; t < 8; t++) {
        if (t < 7) load_tile((t + 1) & 1, t + 1);
        if (t < 7) asm volatile("cp.async.wait_group 1;" ::: "memory");
        else       asm volatile("cp.async.wait_group 0;" ::: "memory");
        __syncthreads();

        const int tb = t & 1;
        #pragma unroll 8
        for (int r = 0; r < 32; r++) {
            unsigned long long w0 = *(const unsigned long long*)&ws[tb][r][tk * 4 + 0];
            unsigned long long w1 = *(const unsigned long long*)&ws[tb][r][tk * 4 + 1];
            unsigned long long w2 = *(const unsigned long long*)&ws[tb][r][tk * 4 + 2];
            unsigned long long w3 = *(const unsigned long long*)&ws[tb][r][tk * 4 + 3];
            #pragma unroll
            for (int i = 0; i < 4; i++) {
                unsigned long long xv =
                    *(const unsigned long long*)&xt[tb][r][(td + 16 * i) * 2];
                acc[0][i] = fma2(xv, w0, acc[0][i]);
                acc[1][i] = fma2(xv, w1, acc[1][i]);
                acc[2][i] = fma2(xv, w2, acc[2][i]);
                acc[3][i] = fma2(xv, w3, acc[3][i]);
            }
        }
        __syncthreads();
    }

    #pragma unroll
    for (int kk = 0; kk < 4; kk++) {
        int k = tk * 4 + kk;
        float* dst = &g_part[(((size_t)b * NSPLIT + sp) * KK + k) * D_ + dbase];
        #pragma unroll
        for (int i = 0; i < 4; i++) {
            float2 v = unpack2(acc[kk][i]);
            *(float2*)&dst[(td + 16 * i) * 2] = v;
        }
    }
}

// ---------------------------------------------------------------------------
// Phase D: reduce split-K partials into soft_slots + expert_inputs, and fill
// expert_weights (1/E) and expert_indices. Fully float4.
// ---------------------------------------------------------------------------
__global__ void __launch_bounds__(256) phaseD(float* __restrict__ out) {
    const int i4 = blockIdx.x * 256 + threadIdx.x; // 65536 float4 threads
    const int b  = i4 >> 13;                       // / (KK*D/4)
    const int rem4 = i4 & 8191;

    const float4* part4 = (const float4*)g_part;
    float4 a = make_float4(0.f, 0.f, 0.f, 0.f);
    #pragma unroll
    for (int sp = 0; sp < NSPLIT; sp++) {
        float4 p = part4[((size_t)b * NSPLIT + sp) * (KK * D_ / 4) + rem4];
        a.x += p.x; a.y += p.y; a.z += p.z; a.w += p.w;
    }
    float4* out4 = (float4*)out;
    out4[OFF3 / 4 + i4] = a;        // soft_slots [B,E,P,D]
    out4[OFF4 / 4 + i4] = a;        // expert_inputs [B,E,P*D] (same layout)
    out4[OFF0 / 4 + i4] = make_float4(0.125f, 0.125f, 0.125f, 0.125f);
    float e0 = (float)((4 * i4) & 7);
    out4[OFF1 / 4 + i4] = make_float4(e0, e0 + 1.f, e0 + 2.f, e0 + 3.f);
}

extern "C" void kernel_launch(void* const* d_in, const int* in_sizes, int n_in,
                              void* d_out, int out_size) {
    const float* x    = (const float*)d_in[0];
    const float* phiK = (const float*)d_in[1];
    const float* bias = (const float*)d_in[2];
    float* out = (float*)d_out;

    phaseA<<<1024, 128>>>(x, phiK, bias);
    phaseB1<<<256, 256>>>();
    phaseB2<<<256, 128>>>(out);
    phaseC<<<1024, 128>>>(x);
    phaseD<<<256, 256>>>(out);
}

// round 9
// speedup vs baseline: 2.9327x; 1.0280x over previous
#include <cuda_runtime.h>
#include <cstdint>

// Problem constants
#define B_  8
#define S_  4096
#define D_  1024
#define KK  32      // E*P = 8*4

// Output layout: flat concat of (expert_weights, expert_indices, phi_weights,
// soft_slots, expert_inputs), all as float32.
#define OFF0 0              // expert_weights [B,S,E]      262144
#define OFF1 262144         // expert_indices [B,S,E]      262144
#define OFF2 524288         // phi_weights    [B,S,E,P]    1048576
#define OFF3 1572864        // soft_slots     [B,E,P,D]    262144
#define OFF4 1835008        // expert_inputs  [B,E,P*D]    262144

#define NSPLIT 16           // S-splits in phaseC
#define NHALF  4            // D-splits in phaseA

// Scratch (device globals: no allocation allowed)
__device__ float  g_Lh[NHALF][B_ * KK * S_];     // logit partials (16 MB); [0] holds sum
__device__ float  g_part[B_ * NSPLIT * KK * D_]; // split-K partials (16 MB)
__device__ float2 g_ms[B_ * KK];                 // per-(b,k) {max, inv_sum}

__device__ __forceinline__ unsigned long long fma2(unsigned long long a,
                                                   unsigned long long b,
                                                   unsigned long long c) {
    unsigned long long d;
    asm("fma.rn.f32x2 %0, %1, %2, %3;" : "=l"(d) : "l"(a), "l"(b), "l"(c));
    return d;
}
__device__ __forceinline__ unsigned long long dup2(float p) {
    unsigned long long d;
    asm("mov.b64 %0, {%1, %1};" : "=l"(d) : "f"(p));
    return d;
}
__device__ __forceinline__ float2 unpack2(unsigned long long v) {
    float2 r;
    asm("mov.b64 {%0, %1}, %2;" : "=f"(r.x), "=f"(r.y) : "l"(v));
    return r;
}
__device__ __forceinline__ void cpa16(uint32_t dst, const void* src) {
    asm volatile("cp.async.cg.shared.global [%0], [%1], 16;" :: "r"(dst), "l"(src));
}
__device__ __forceinline__ void cpa_commit() {
    asm volatile("cp.async.commit_group;");
}

// ---------------------------------------------------------------------------
// Phase A: partial logits over a quarter of D, cp.async double-buffered.
// Grid 1024: bid = tile*4 + half. Tile = 128 tokens x 32 k.
// f32x2 pairs over k: x stays in natural [tok][d] layout (cp.async direct),
// x scalar broadcast per 4-lane k-group, phi pairs via LDS.64.
// ---------------------------------------------------------------------------
__global__ void __launch_bounds__(128) phaseA(const float* __restrict__ x,
                                              const float* __restrict__ phiK,
                                              const float* __restrict__ bias) {
    __shared__ __align__(16) float xs[2][128][36]; // [buf][tok][d] (+pad)
    __shared__ __align__(16) float ps[2][32][32];  // [buf][d][k]

    const int tid  = threadIdx.x;
    const int bid  = blockIdx.x;
    const int half = bid & 3;
    const int tile = bid >> 2;
    const int tok0 = tile * 128;                // never crosses a batch
    const int b    = tok0 / S_;
    const int s0   = tok0 - b * S_;
    const int kt   = tid & 3;                   // k-group: 8 k = 4 pairs
    const int tokt = tid >> 2;                  // token lane: 4 tokens stride 32

    unsigned long long acc[4][4];               // [token i][k-pair j]
    #pragma unroll
    for (int i = 0; i < 4; i++)
        #pragma unroll
        for (int j = 0; j < 4; j++) acc[i][j] = 0ull;

    const float* xbase = x + (size_t)tok0 * D_ + half * 256;

    auto load_tile = [&](int tb, int dt) {
        const int dbase = dt * 32;
        #pragma unroll
        for (int j = 0; j < 8; j++) {           // x: 128 tok x 32 d = 1024 chunks
            int chunk = tid + j * 128;
            int row = chunk >> 3;
            int c   = chunk & 7;
            cpa16((uint32_t)__cvta_generic_to_shared(&xs[tb][row][c * 4]),
                  xbase + (size_t)row * D_ + dbase + c * 4);
        }
        #pragma unroll
        for (int j = 0; j < 2; j++) {           // phi: 32 d x 32 k = 256 chunks
            int chunk = tid + j * 128;
            int d = chunk >> 3;
            int c = chunk & 7;
            cpa16((uint32_t)__cvta_generic_to_shared(&ps[tb][d][c * 4]),
                  phiK + (size_t)(half * 256 + dbase + d) * KK + c * 4);
        }
        cpa_commit();
    };

    load_tile(0, 0);

    #pragma unroll
    for (int t = 0; t < 8; t++) {
        if (t < 7) load_tile((t + 1) & 1, t + 1);
        if (t < 7) asm volatile("cp.async.wait_group 1;" ::: "memory");
        else       asm volatile("cp.async.wait_group 0;" ::: "memory");
        __syncthreads();

        const int tb = t & 1;
        #pragma unroll 8
        for (int d = 0; d < 32; d++) {
            unsigned long long p0 = *(const unsigned long long*)&ps[tb][d][kt * 8 + 0];
            unsigned long long p1 = *(const unsigned long long*)&ps[tb][d][kt * 8 + 2];
            unsigned long long p2 = *(const unsigned long long*)&ps[tb][d][kt * 8 + 4];
            unsigned long long p3 = *(const unsigned long long*)&ps[tb][d][kt * 8 + 6];
            #pragma unroll
            for (int i = 0; i < 4; i++) {
                unsigned long long xv = dup2(xs[tb][tokt + 32 * i][d]);
                acc[i][0] = fma2(xv, p0, acc[i][0]);
                acc[i][1] = fma2(xv, p1, acc[i][1]);
                acc[i][2] = fma2(xv, p2, acc[i][2]);
                acc[i][3] = fma2(xv, p3, acc[i][3]);
            }
        }
        __syncthreads();
    }

    float bv[8];
    #pragma unroll
    for (int j = 0; j < 8; j++)
        bv[j] = (half == 0) ? bias[kt * 8 + j] : 0.f;

    float* Ldst = g_Lh[half] + (size_t)b * KK * S_ + s0;
    #pragma unroll
    for (int i = 0; i < 4; i++) {
        int tok = tokt + 32 * i;
        #pragma unroll
        for (int j = 0; j < 4; j++) {
            float2 v = unpack2(acc[i][j]);
            int k0 = kt * 8 + 2 * j;
            Ldst[(size_t)k0 * S_ + tok]       = v.x + bv[2 * j];
            Ldst[(size_t)(k0 + 1) * S_ + tok] = v.y + bv[2 * j + 1];
        }
    }
}

// ---------------------------------------------------------------------------
// Phase B1: sum the 4 logit partials (write back to g_Lh[0]) and compute
// per-(b,k) softmax stats {max, 1/sum(exp)}. float4 loads.
// ---------------------------------------------------------------------------
__global__ void __launch_bounds__(256) phaseB1() {
    const int bk  = blockIdx.x;       // b*32 + k
    const int tid = threadIdx.x;
    const size_t base4 = (size_t)bk * (S_ / 4);
    float4* L0       = (float4*)g_Lh[0] + base4;
    const float4* L1 = (const float4*)g_Lh[1] + base4;
    const float4* L2 = (const float4*)g_Lh[2] + base4;
    const float4* L3 = (const float4*)g_Lh[3] + base4;

    __shared__ float red[8];

    float4 v[4];
    float m = -1e30f;
    #pragma unroll
    for (int i = 0; i < 4; i++) {
        int idx = tid + i * 256;
        float4 a = L0[idx], b4 = L1[idx], c = L2[idx], d = L3[idx];
        a.x += b4.x + c.x + d.x;
        a.y += b4.y + c.y + d.y;
        a.z += b4.z + c.z + d.z;
        a.w += b4.w + c.w + d.w;
        v[i] = a;
        L0[idx] = a;
        m = fmaxf(m, fmaxf(fmaxf(a.x, a.y), fmaxf(a.z, a.w)));
    }
    #pragma unroll
    for (int o = 16; o > 0; o >>= 1) m = fmaxf(m, __shfl_xor_sync(0xffffffffu, m, o));
    if ((tid & 31) == 0) red[tid >> 5] = m;
    __syncthreads();
    if (tid < 32) {
        float t = (tid < 8) ? red[tid] : -1e30f;
        #pragma unroll
        for (int o = 4; o > 0; o >>= 1) t = fmaxf(t, __shfl_xor_sync(0xffffffffu, t, o));
        if (tid == 0) red[0] = t;
    }
    __syncthreads();
    m = red[0];
    __syncthreads();

    float s = 0.f;
    #pragma unroll
    for (int i = 0; i < 4; i++) {
        s += __expf(v[i].x - m) + __expf(v[i].y - m)
           + __expf(v[i].z - m) + __expf(v[i].w - m);
    }
    #pragma unroll
    for (int o = 16; o > 0; o >>= 1) s += __shfl_xor_sync(0xffffffffu, s, o);
    if ((tid & 31) == 0) red[tid >> 5] = s;
    __syncthreads();
    if (tid < 32) {
        float t = (tid < 8) ? red[tid] : 0.f;
        #pragma unroll
        for (int o = 4; o > 0; o >>= 1) t += __shfl_xor_sync(0xffffffffu, t, o);
        if (tid == 0) red[0] = t;
    }
    __syncthreads();
    if (tid == 0) {
        float2 r; r.x = m; r.y = 1.0f / red[0];
        g_ms[bk] = r;
    }
}

// ---------------------------------------------------------------------------
// Phase B2: normalize + transpose. Reads g_Lh[0][k][s] coalesced, writes
// phi_weights [b][s][k] with STG.128.
// ---------------------------------------------------------------------------
__global__ void __launch_bounds__(128) phaseB2(float* __restrict__ out) {
    const int bid = blockIdx.x;           // b*32 + stile
    const int b   = bid >> 5;
    const int s0  = (bid & 31) * 128;
    const int tid = threadIdx.x;

    __shared__ float  sm[32][129];
    __shared__ float2 ms[32];

    if (tid < 32) ms[tid] = g_ms[b * KK + tid];
    __syncthreads();

    #pragma unroll
    for (int k = 0; k < 32; k++) {
        float v = g_Lh[0][((size_t)b * KK + k) * S_ + s0 + tid];
        sm[k][tid] = __expf(v - ms[k].x) * ms[k].y;
    }
    __syncthreads();

    float* dst = out + OFF2 + ((size_t)b * S_ + s0 + tid) * KK;
    #pragma unroll
    for (int k4 = 0; k4 < 8; k4++) {
        float4 v;
        v.x = sm[k4 * 4 + 0][tid];
        v.y = sm[k4 * 4 + 1][tid];
        v.z = sm[k4 * 4 + 2][tid];
        v.w = sm[k4 * 4 + 3][tid];
        *(float4*)&dst[k4 * 4] = v;
    }
}

// ---------------------------------------------------------------------------
// Phase C (R5 form — measured 49.4us): partial[b,sp,k,d] over S-split sp.
// cp.async double-buffered compact tiles; w via LDS.128 + in-register dup2.
// ---------------------------------------------------------------------------
__global__ void __launch_bounds__(128) phaseC(const float* __restrict__ x,
                                              const float* __restrict__ out) {
    const int bid = blockIdx.x;
    const int b   = bid >> 7;
    const int dt  = (bid >> 4) & 7;
    const int sp  = bid & 15;
    const int dbase = dt * 128;
    const int tid = threadIdx.x;
    const int td  = tid & 15;   // d-pair lane
    const int tk  = tid >> 4;   // k group: 4 contiguous k

    __shared__ __align__(16) float xt[2][32][132]; // [buf][s][d]
    __shared__ __align__(16) float ws[2][32][36];  // [buf][s][k]

    unsigned long long acc[4][4]; // [kk][d-pair i]
    #pragma unroll
    for (int i = 0; i < 4; i++)
        #pragma unroll
        for (int j = 0; j < 4; j++) acc[i][j] = 0ull;

    const float* w    = out + OFF2 + (size_t)b * S_ * KK;
    const float* xrow = x + (size_t)b * S_ * D_ + dbase;

    auto load_tile = [&](int tb, int t) {
        const int sb = sp * 256 + t * 32;
        #pragma unroll
        for (int j = 0; j < 8; j++) {          // x: 1024 16B chunks / 128 thr
            int chunk = tid + j * 128;
            int row = chunk >> 5;
            int c   = chunk & 31;
            cpa16((uint32_t)__cvta_generic_to_shared(&xt[tb][row][c * 4]),
                  xrow + (size_t)(sb + row) * D_ + c * 4);
        }
        #pragma unroll
        for (int j = 0; j < 2; j++) {          // w: 256 16B chunks / 128 thr
            int chunk = tid + j * 128;
            int row = chunk >> 3;
            int c   = chunk & 7;
            cpa16((uint32_t)__cvta_generic_to_shared(&ws[tb][row][c * 4]),
                  w + (size_t)(sb + row) * KK + c * 4);
        }
        cpa_commit();
    };

    load_tile(0, 0);

    #pragma unroll
    for (int t = 0; t < 8; t++) {
        if (t < 7) load_tile((t + 1) & 1, t + 1);
        if (t < 7) asm volatile("cp.async.wait_group 1;" ::: "memory");
        else       asm volatile("cp.async.wait_group 0;" ::: "memory");
        __syncthreads();

        const int tb = t & 1;
        #pragma unroll 8
        for (int r = 0; r < 32; r++) {
            float4 wv = *(const float4*)&ws[tb][r][tk * 4];
            unsigned long long w0 = dup2(wv.x), w1 = dup2(wv.y),
                               w2 = dup2(wv.z), w3 = dup2(wv.w);
            #pragma unroll
            for (int i = 0; i < 4; i++) {
                unsigned long long xv =
                    *(const unsigned long long*)&xt[tb][r][(td + 16 * i) * 2];
                acc[0][i] = fma2(xv, w0, acc[0][i]);
                acc[1][i] = fma2(xv, w1, acc[1][i]);
                acc[2][i] = fma2(xv, w2, acc[2][i]);
                acc[3][i] = fma2(xv, w3, acc[3][i]);
            }
        }
        __syncthreads();
    }

    #pragma unroll
    for (int kk = 0; kk < 4; kk++) {
        int k = tk * 4 + kk;
        float* dst = &g_part[(((size_t)b * NSPLIT + sp) * KK + k) * D_ + dbase];
        #pragma unroll
        for (int i = 0; i < 4; i++) {
            float2 v = unpack2(acc[kk][i]);
            *(float2*)&dst[(td + 16 * i) * 2] = v;
        }
    }
}

// ---------------------------------------------------------------------------
// Phase D: reduce split-K partials into soft_slots + expert_inputs, and fill
// expert_weights (1/E) and expert_indices. Fully float4.
// ---------------------------------------------------------------------------
__global__ void __launch_bounds__(256) phaseD(float* __restrict__ out) {
    const int i4 = blockIdx.x * 256 + threadIdx.x; // 65536 float4 threads
    const int b  = i4 >> 13;                       // / (KK*D/4)
    const int rem4 = i4 & 8191;

    const float4* part4 = (const float4*)g_part;
    float4 a = make_float4(0.f, 0.f, 0.f, 0.f);
    #pragma unroll
    for (int sp = 0; sp < NSPLIT; sp++) {
        float4 p = part4[((size_t)b * NSPLIT + sp) * (KK * D_ / 4) + rem4];
        a.x += p.x; a.y += p.y; a.z += p.z; a.w += p.w;
    }
    float4* out4 = (float4*)out;
    out4[OFF3 / 4 + i4] = a;        // soft_slots [B,E,P,D]
    out4[OFF4 / 4 + i4] = a;        // expert_inputs [B,E,P*D] (same layout)
    out4[OFF0 / 4 + i4] = make_float4(0.125f, 0.125f, 0.125f, 0.125f);
    float e0 = (float)((4 * i4) & 7);
    out4[OFF1 / 4 + i4] = make_float4(e0, e0 + 1.f, e0 + 2.f, e0 + 3.f);
}

extern "C" void kernel_launch(void* const* d_in, const int* in_sizes, int n_in,
                              void* d_out, int out_size) {
    const float* x    = (const float*)d_in[0];
    const float* phiK = (const float*)d_in[1];
    const float* bias = (const float*)d_in[2];
    float* out = (float*)d_out;

    phaseA<<<1024, 128>>>(x, phiK, bias);
    phaseB1<<<256, 256>>>();
    phaseB2<<<256, 128>>>(out);
    phaseC<<<1024, 128>>>(x, out);
    phaseD<<<256, 256>>>(out);
}